// round 1
// baseline (speedup 1.0000x reference)
#include <cuda_runtime.h>
#include <cuda_bf16.h>
#include <cstdint>

// MatrixExpander: out(B,C,512,512) = kron(A(B,C,64,64), ones(8,8))
// B=C=16, Ar=Ac=64, mp=8. Pure write-bandwidth kernel.
//
// One float4 store per thread: 512 floats/row = 128 float4/row.
// float4-col index c4 in [0,128): output cols [c4*4, c4*4+4) all map to
// A col (c4*4)>>3 = c4>>1. Output row r maps to A row r>>3.
// Warp of 32 threads -> 512 contiguous bytes per STG.128: perfect coalescing.

__global__ __launch_bounds__(256)
void expander_kernel(const float* __restrict__ A, float4* __restrict__ out)
{
    // total float4s = 16*16*512*512/4 = 16,777,216 = 1<<24
    const uint32_t i = blockIdx.x * 256u + threadIdx.x;

    const uint32_t c4  = i & 127u;          // float4 column within row [0,128)
    const uint32_t row = (i >> 7) & 511u;   // output row [0,512)
    const uint32_t bc  = i >> 16;           // fused (b,c) [0,256)

    const uint32_t acol = c4 >> 1;          // [0,64)
    const uint32_t arow = row >> 3;         // [0,64)

    const float v = __ldg(A + ((bc << 12) | (arow << 6) | acol));
    out[i] = make_float4(v, v, v, v);
}

extern "C" void kernel_launch(void* const* d_in, const int* in_sizes, int n_in,
                              void* d_out, int out_size)
{
    const float* A = (const float*)d_in[0];   // (16,16,64,64) fp32
    float4* out = (float4*)d_out;             // (16,16,512,512) fp32

    // 1<<24 float4s / 256 threads = 65536 blocks
    expander_kernel<<<65536, 256>>>(A, out);
}

// round 2
// speedup vs baseline: 1.2653x; 1.2653x over previous
#include <cuda_runtime.h>
#include <cuda_bf16.h>
#include <cstdint>

// MatrixExpander: out(16,16,512,512) = kron(A(16,16,64,64), ones(8,8)), fp32.
//
// Key structural fact: tile c = (bc*64 + arow) covers output rows
// [arow*8, arow*8+8) of image bc -> a CONTIGUOUS 16 KB span at out + c*4096
// floats, whose content is the expanded A-row (512 floats) repeated 8x.
// Likewise its source is the contiguous 64-float span A + c*64.
//
// Strategy: build the 16 KB tile in SMEM (cheap STS), then push it with ONE
// 1D TMA bulk store (cp.async.bulk shared->global). This removes the
// per-thread STG.128 / L1tex path and the LDG->STG dependency chain that
// capped R1 at ~5 TB/s with DRAM only 50% busy.

__device__ __forceinline__ uint32_t smem_u32(const void* p) {
    uint32_t a;
    asm("{ .reg .u64 t; cvta.to.shared.u64 t, %1; cvt.u32.u64 %0, t; }"
        : "=r"(a) : "l"(p));
    return a;
}

__global__ __launch_bounds__(256)
void expander_tma_kernel(const float* __restrict__ A, float* __restrict__ out)
{
    __shared__ __align__(128) float4 buf[1024];   // 16 KB = 8 output rows

    const uint32_t c = blockIdx.x;   // tile id in [0, 16384)
    const uint32_t t = threadIdx.x;  // [0, 256)

    // Thread t fills float4 slots 4t..4t+3 of buf.
    // Slot f -> output col4 = f & 127 -> A col = (f & 127) >> 1.
    // For f = 4t+k: k=0,1 -> A[(2t)&63], k=2,3 -> A[(2t+1)&63].
    // Row (f>>7) is irrelevant: all 8 rows share the same expanded content.
    const float2 av = *reinterpret_cast<const float2*>(
        A + (c << 6) + ((2u * t) & 63u));

    const float4 v0 = make_float4(av.x, av.x, av.x, av.x);
    const float4 v1 = make_float4(av.y, av.y, av.y, av.y);
    buf[4u * t + 0] = v0;
    buf[4u * t + 1] = v0;
    buf[4u * t + 2] = v1;
    buf[4u * t + 3] = v1;

    __syncthreads();

    if (t == 0) {
        // Order generic-proxy STS before async-proxy bulk read.
        asm volatile("fence.proxy.async.shared::cta;" ::: "memory");
        const uint32_t s = smem_u32(buf);
        const float* dst = out + ((size_t)c << 12);   // c * 4096 floats = c * 16 KB
        asm volatile(
            "cp.async.bulk.global.shared::cta.bulk_group [%0], [%1], %2;"
            :: "l"(dst), "r"(s), "n"(16384) : "memory");
        asm volatile("cp.async.bulk.commit_group;" ::: "memory");
        asm volatile("cp.async.bulk.wait_group 0;" ::: "memory");
    }
}

extern "C" void kernel_launch(void* const* d_in, const int* in_sizes, int n_in,
                              void* d_out, int out_size)
{
    const float* A = (const float*)d_in[0];   // (16,16,64,64) fp32
    float* out = (float*)d_out;               // (16,16,512,512) fp32

    // 16384 tiles of 16 KB = 256 MiB output
    expander_tma_kernel<<<16384, 256>>>(A, out);
}